// round 14
// baseline (speedup 1.0000x reference)
#include <cuda_runtime.h>
#include <cstdint>

// Problem constants (fixed by the dataset)
#define BB    4
#define NBC   128
#define NINT  4096
#define HID   64

#define NBC_CHK  64
#define NCHUNK   (NBC / NBC_CHK)      // 2

// ---------------------------------------------------------------------------
// Device scratch (allocation-free)
// ---------------------------------------------------------------------------
__device__ float g_avec[BB * NBC * HID];              // a[b][nbc][k]

// ---------------------------------------------------------------------------
// fp16 helpers (plain sm_80+)
// ---------------------------------------------------------------------------
__device__ __forceinline__ uint32_t pack_f16x2(float lo, float hi) {
    uint32_t r;
    asm("cvt.rn.f16x2.f32 %0, %1, %2;" : "=r"(r) : "f"(hi), "f"(lo));
    return r;
}
__device__ __forceinline__ uint32_t add_f16x2(uint32_t a, uint32_t b) {
    uint32_t r;
    asm("add.f16x2 %0, %1, %2;" : "=r"(r) : "r"(a), "r"(b));
    return r;
}
__device__ __forceinline__ uint32_t relu_f16x2(uint32_t a) {
    uint32_t r;
    asm("max.f16x2 %0, %1, %2;" : "=r"(r) : "r"(a), "r"(0u));
    return r;
}
// f16-accum MMA, C given explicitly (bias fold, no init MOVs)
__device__ __forceinline__ void mma_f16_init(uint32_t& d0, uint32_t& d1,
                                             uint32_t a0, uint32_t a1, uint32_t a2, uint32_t a3,
                                             uint32_t b0, uint32_t b1, uint32_t c) {
    asm volatile("mma.sync.aligned.m16n8k16.row.col.f16.f16.f16.f16 "
                 "{%0,%1}, {%2,%3,%4,%5}, {%6,%7}, {%8,%8};"
                 : "=r"(d0), "=r"(d1)
                 : "r"(a0), "r"(a1), "r"(a2), "r"(a3), "r"(b0), "r"(b1), "r"(c));
}
__device__ __forceinline__ void mma_f16_acc(uint32_t& d0, uint32_t& d1,
                                            uint32_t a0, uint32_t a1, uint32_t a2, uint32_t a3,
                                            uint32_t b0, uint32_t b1) {
    asm volatile("mma.sync.aligned.m16n8k16.row.col.f16.f16.f16.f16 "
                 "{%0,%1}, {%2,%3,%4,%5}, {%6,%7}, {%0,%1};"
                 : "+r"(d0), "+r"(d1)
                 : "r"(a0), "r"(a1), "r"(a2), "r"(a3), "r"(b0), "r"(b1));
}
// f32-accum epilogue MMA (f16 inputs)
__device__ __forceinline__ void mma_f16_f32(float& d0, float& d1, float& d2, float& d3,
                                            uint32_t a0, uint32_t a1, uint32_t a2, uint32_t a3,
                                            uint32_t b0, uint32_t b1) {
    asm volatile("mma.sync.aligned.m16n8k16.row.col.f32.f16.f16.f32 "
                 "{%0,%1,%2,%3}, {%4,%5,%6,%7}, {%8,%9}, {%0,%1,%2,%3};"
                 : "+f"(d0), "+f"(d1), "+f"(d2), "+f"(d3)
                 : "r"(a0), "r"(a1), "r"(a2), "r"(a3), "r"(b0), "r"(b1));
}

__device__ __forceinline__ uint32_t smem_u32(const void* p) {
    uint32_t a;
    asm("{ .reg .u64 t; cvta.to.shared.u64 t, %1; cvt.u32.u64 %0, t; }" : "=r"(a) : "l"(p));
    return a;
}
__device__ __forceinline__ void cp_async16(uint32_t saddr, const void* g) {
    asm volatile("cp.async.cg.shared.global [%0], [%1], 16;" :: "r"(saddr), "l"(g));
}

// ---------------------------------------------------------------------------
// prepA kernel: per (b,nbc): bf = relu(relu(binfo@W0+b0)@W1+b1); a = bf@G0w[:64]
// 256 blocks x 128 threads (2 boundary points per block).
// Also zeroes d_out (64 floats per block) for the atomic accumulation in main.
// ---------------------------------------------------------------------------
__global__ void __launch_bounds__(128)
prepA_kernel(const float* __restrict__ binfo,
             const float* __restrict__ W0, const float* __restrict__ b0,
             const float* __restrict__ W1, const float* __restrict__ b1,
             const float* __restrict__ G0w,
             float* __restrict__ out) {
    __shared__ __align__(16) float sW1[HID * HID];
    __shared__ __align__(16) float sG0[HID * HID];
    __shared__ float sbf0[2][HID];
    __shared__ float sbf1[2][HID];

    const int tid = threadIdx.x;
    const int sub = tid >> 6;       // 0..1
    const int j   = tid & 63;
    const int bn  = blockIdx.x * 2 + sub;    // 0..511

    {   // async prefetch of big weights (overlaps with stage 0)
        uint32_t sw = smem_u32(sW1);
        uint32_t sg = smem_u32(sG0);
        #pragma unroll
        for (int i = tid; i < 1024; i += 128) cp_async16(sw + i * 16, W1 + i * 4);
        #pragma unroll
        for (int i = tid; i < 1024; i += 128) cp_async16(sg + i * 16, G0w + i * 4);
        asm volatile("cp.async.commit_group;" ::: "memory");
    }

    // zero the output slice this block owns (BB*NINT = 16384 = 256 blocks * 64)
    if (tid < 64) out[blockIdx.x * 64 + tid] = 0.0f;

    // stage 0: bf0 = relu(binfo @ W0 + b0)
    const float* bi = binfo + bn * 3;
    float x0 = bi[0], x1 = bi[1], x2 = bi[2];
    sbf0[sub][j] = fmaxf(
        fmaf(x0, W0[j], fmaf(x1, W0[64 + j], fmaf(x2, W0[128 + j], b0[j]))), 0.0f);

    asm volatile("cp.async.wait_group 0;" ::: "memory");
    __syncthreads();

    // stage 1: bf1 = relu(bf0 @ W1 + b1)
    float s = b1[j];
    #pragma unroll 16
    for (int k = 0; k < HID; k++) s = fmaf(sbf0[sub][k], sW1[k * 64 + j], s);
    sbf1[sub][j] = fmaxf(s, 0.0f);
    __syncthreads();

    // stage 2: a = bf1 @ G0w[:64]
    float a = 0.0f;
    #pragma unroll 16
    for (int k = 0; k < HID; k++) a = fmaf(sbf1[sub][k], sG0[k * 64 + j], a);
    g_avec[bn * 64 + j] = a;
}

// ---------------------------------------------------------------------------
// Main kernel: fp16 m16n8k16, n-split warp layout.
// 8 warps = 4 m-blocks x 2 n-halves; each warp owns m16 x n32 -> ALL B
// fragments live in 32 registers, zero B-LDS in the loop. Bias via C operand;
// second-GEMM epilogue (f16 in, f32 accum) covers the warp's j-half; the
// 4 contributions per row (2 chunks x 2 halves) merge via atomicAdd
// (fixed addend set -> deterministic). grid (64,4,2)=512 CTAs @ 2/SM.
// ---------------------------------------------------------------------------
#define WSTRIDE 68   // uint2 units per packed row (prologue staging only)

// smem: s_ap2 64*16 uint2 (8192B) | s_w 16*68 uint2 (8704B) | 3*64 f (768B)
#define SMEM_AP_BYTES 8192
#define SMEM_W_BYTES  (16 * WSTRIDE * 8)
#define SMEM_WX_OFF   (SMEM_AP_BYTES + SMEM_W_BYTES)
#define SMEM_TOTAL    (SMEM_WX_OFF + 3 * 64 * 4)

__global__ void __launch_bounds__(256, 2)
main_kernel(const float* __restrict__ G1w,
            const float* __restrict__ G1b,
            const float* __restrict__ G2w,
            const float* __restrict__ G2b,
            const float* __restrict__ coords,
            const float* __restrict__ G0w,
            const float* __restrict__ G0b,
            float* __restrict__ out) {
    extern __shared__ char smem[];
    uint2* s_ap2 = reinterpret_cast<uint2*>(smem);
    uint2* s_w   = reinterpret_cast<uint2*>(smem + SMEM_AP_BYTES);
    float* s_wx  = reinterpret_cast<float*>(smem + SMEM_WX_OFF);
    float* s_wy  = s_wx + 64;
    float* s_gb  = s_wy + 64;

    const int tid   = threadIdx.x;
    const int wid   = tid >> 5;
    const int lane  = tid & 31;
    const int gid   = lane >> 2;    // 0..7
    const int tig   = lane & 3;     // 0..3
    const int mblk  = wid >> 1;     // 0..3  (m16 row-block within CTA)
    const int nh    = wid & 1;      // 0..1  (n-half: cols [nh*32, nh*32+32))
    const int tile  = blockIdx.x;   // 0..63
    const int b     = blockIdx.y;   // 0..3
    const int chunk = blockIdx.z;   // 0..1
    const int rowl  = tile * 64 + mblk * 16 + gid;   // local row within batch
    const int row0  = b * NINT + rowl;               // global row (i)

    // --- cooperative smem init ---
    {   // a for this (batch, chunk) packed in A-fragment pair order (fp16)
        const float* abase = g_avec + ((size_t)b * NBC + chunk * NBC_CHK) * HID;
        #pragma unroll
        for (int idx = tid; idx < NBC_CHK * 16; idx += 256) {
            int nn = idx >> 4;
            int p  = idx & 15;
            int s  = p >> 2;
            int t  = p & 3;
            const float* row = abase + nn * 64 + 16 * s + 2 * t;
            float2 lo = *reinterpret_cast<const float2*>(row);
            float2 hi = *reinterpret_cast<const float2*>(row + 8);
            s_ap2[idx] = make_uint2(pack_f16x2(lo.x, lo.y), pack_f16x2(hi.x, hi.y));
        }
    }
    {   // G1w -> fp16, packed per (s,tg): {W[k0],W[k0+1]} , {W[k0+8],W[k0+9]}
        #pragma unroll
        for (int idx = tid; idx < 16 * 64; idx += 256) {
            int prow = idx >> 6;            // 0..15 = s*4 + tg
            int col  = idx & 63;
            int s    = prow >> 2;
            int tg   = prow & 3;
            int k0   = 16 * s + 2 * tg;
            uint32_t w0 = pack_f16x2(G1w[k0 * 64 + col],       G1w[(k0 + 1) * 64 + col]);
            uint32_t w1 = pack_f16x2(G1w[(k0 + 8) * 64 + col], G1w[(k0 + 9) * 64 + col]);
            s_w[prow * WSTRIDE + col] = make_uint2(w0, w1);
        }
    }
    if (tid < 64) {
        s_wx[tid] = G0w[64 * 64 + tid];
        s_wy[tid] = G0w[65 * 64 + tid];
        s_gb[tid] = G0b[tid];
    }
    __syncthreads();

    // --- loop-invariant registers ---
    // c packed f16x2 (rows row0 / row0+8), k-pairs (16s+2tig{,+1}) and (+8{,+9})
    uint32_t cp0[8], cp1[8];
    {
        float cx0 = coords[(size_t)row0 * 2 + 0];
        float cy0 = coords[(size_t)row0 * 2 + 1];
        float cx1 = coords[(size_t)(row0 + 8) * 2 + 0];
        float cy1 = coords[(size_t)(row0 + 8) * 2 + 1];
        #pragma unroll
        for (int s = 0; s < 4; s++) {
            #pragma unroll
            for (int h = 0; h < 2; h++) {
                int k = 16 * s + 2 * tig + 8 * h;
                float wxa = s_wx[k],     wya = s_wy[k],     gba = s_gb[k];
                float wxb = s_wx[k + 1], wyb = s_wy[k + 1], gbb = s_gb[k + 1];
                cp0[2 * s + h] = pack_f16x2(fmaf(cx0, wxa, fmaf(cy0, wya, gba)),
                                            fmaf(cx0, wxb, fmaf(cy0, wyb, gbb)));
                cp1[2 * s + h] = pack_f16x2(fmaf(cx1, wxa, fmaf(cy1, wya, gba)),
                                            fmaf(cx1, wxb, fmaf(cy1, wyb, gbb)));
            }
        }
    }
    // ALL B fragments for this warp's 4 n-blocks (global nb = nh*4 + nb): 32 regs
    uint2 bw[4][4];
    #pragma unroll
    for (int nb = 0; nb < 4; nb++) {
        const int col = (nh * 4 + nb) * 8 + gid;
        #pragma unroll
        for (int s = 0; s < 4; s++)
            bw[nb][s] = s_w[(s * 4 + tig) * WSTRIDE + col];
    }
    // bias C-operands for this warp's n-blocks
    uint32_t bb[4];
    #pragma unroll
    for (int nb = 0; nb < 4; nb++) {
        float2 g = *reinterpret_cast<const float2*>(G1b + (nh * 4 + nb) * 8 + 2 * tig);
        bb[nb] = pack_f16x2(g.x, g.y);
    }
    // second-GEMM B fragments: g2w j-rows for this warp's half, n-replicated
    uint2 b2[2];
    #pragma unroll
    for (int kc = 0; kc < 2; kc++) {
        int k = nh * 32 + 16 * kc + 2 * tig;
        float2 glo = *reinterpret_cast<const float2*>(G2w + k);
        float2 ghi = *reinterpret_cast<const float2*>(G2w + k + 8);
        b2[kc] = make_uint2(pack_f16x2(glo.x, glo.y), pack_f16x2(ghi.x, ghi.y));
    }

    // persistent second-GEMM accumulators (2 chains)
    float Da0 = 0.0f, Da1 = 0.0f, Da2 = 0.0f, Da3 = 0.0f;
    float Db0 = 0.0f, Db1 = 0.0f, Db2 = 0.0f, Db3 = 0.0f;

    #pragma unroll 1
    for (int nn = 0; nn < NBC_CHK; nn++) {
        const uint2* ar = s_ap2 + nn * 16;

        // A fragments: h1 = relu(a + c), f16x2 (only 4 LDS.64 per iter)
        uint32_t A0[4], A1[4], A2v[4], A3[4];
        #pragma unroll
        for (int s = 0; s < 4; s++) {
            uint2 ap = ar[s * 4 + tig];
            A0[s]  = relu_f16x2(add_f16x2(ap.x, cp0[2 * s + 0]));   // row gid,   k,k+1
            A1[s]  = relu_f16x2(add_f16x2(ap.x, cp1[2 * s + 0]));   // row gid+8, k,k+1
            A2v[s] = relu_f16x2(add_f16x2(ap.y, cp0[2 * s + 1]));   // row gid,   k+8,k+9
            A3[s]  = relu_f16x2(add_f16x2(ap.y, cp1[2 * s + 1]));   // row gid+8, k+8,k+9
        }

        #pragma unroll
        for (int kc = 0; kc < 2; kc++) {
            const int nb0 = 2 * kc, nb1 = 2 * kc + 1;
            uint32_t d0, d1, f0, f1;
            mma_f16_init(d0, d1, A0[0], A1[0], A2v[0], A3[0],
                         bw[nb0][0].x, bw[nb0][0].y, bb[nb0]);
            #pragma unroll
            for (int s = 1; s < 4; s++)
                mma_f16_acc(d0, d1, A0[s], A1[s], A2v[s], A3[s],
                            bw[nb0][s].x, bw[nb0][s].y);
            mma_f16_init(f0, f1, A0[0], A1[0], A2v[0], A3[0],
                         bw[nb1][0].x, bw[nb1][0].y, bb[nb1]);
            #pragma unroll
            for (int s = 1; s < 4; s++)
                mma_f16_acc(f0, f1, A0[s], A1[s], A2v[s], A3[s],
                            bw[nb1][s].x, bw[nb1][s].y);
            // relu(h2) -> epilogue A fragments (layout matches directly)
            d0 = relu_f16x2(d0);
            d1 = relu_f16x2(d1);
            f0 = relu_f16x2(f0);
            f1 = relu_f16x2(f1);
            if (kc & 1)
                mma_f16_f32(Db0, Db1, Db2, Db3, d0, d1, f0, f1, b2[kc].x, b2[kc].y);
            else
                mma_f16_f32(Da0, Da1, Da2, Da3, d0, d1, f0, f1, b2[kc].x, b2[kc].y);
        }
    }

    // D2 n-columns identical (B replicated) -> no reduction; atomically merge
    // the 4 contributions per row (2 chunks x 2 n-halves) into out.
    if (tig == 0) {
        const float scale = 1.0f / (float)NBC;
        const float gb2   = G2b[0] * (1.0f / (float)(NCHUNK * 2));
        atomicAdd(out + row0,     fmaf(Da0 + Db0, scale, gb2));
        atomicAdd(out + row0 + 8, fmaf(Da2 + Db2, scale, gb2));
    }
}

// ---------------------------------------------------------------------------
// Launch.  Inputs (metadata order):
// 0 boundary_info 1 interior_coords 2 W0 3 b0 4 W1 5 b1
// 6 G0w 7 G0b 8 G1w 9 G1b 10 G2w 11 G2b 12 interior_h 13 interior_w
// ---------------------------------------------------------------------------
extern "C" void kernel_launch(void* const* d_in, const int* in_sizes, int n_in,
                              void* d_out, int out_size) {
    const float* binfo  = (const float*)d_in[0];
    const float* coords = (const float*)d_in[1];
    const float* W0     = (const float*)d_in[2];
    const float* b0     = (const float*)d_in[3];
    const float* W1     = (const float*)d_in[4];
    const float* b1     = (const float*)d_in[5];
    const float* G0w    = (const float*)d_in[6];
    const float* G0b    = (const float*)d_in[7];
    const float* G1w    = (const float*)d_in[8];
    const float* G1b    = (const float*)d_in[9];
    const float* G2w    = (const float*)d_in[10];
    const float* G2b    = (const float*)d_in[11];
    float* out          = (float*)d_out;

    cudaFuncSetAttribute(main_kernel, cudaFuncAttributeMaxDynamicSharedMemorySize, SMEM_TOTAL);

    prepA_kernel<<<256, 128>>>(binfo, W0, b0, W1, b1, G0w, out);
    main_kernel<<<dim3(NINT / 64, BB, NCHUNK), 256, SMEM_TOTAL>>>(
        G1w, G1b, G2w, G2b, coords, G0w, G0b, out);
}

// round 15
// speedup vs baseline: 1.1183x; 1.1183x over previous
#include <cuda_runtime.h>
#include <cstdint>

// Problem constants (fixed by the dataset)
#define BB    4
#define NBC   128
#define NINT  4096
#define HID   64

// ---------------------------------------------------------------------------
// Device scratch (allocation-free)
// ---------------------------------------------------------------------------
__device__ float g_avec[BB * NBC * HID];              // a[b][nbc][k]

// ---------------------------------------------------------------------------
// fp16 helpers (plain sm_80+)
// ---------------------------------------------------------------------------
__device__ __forceinline__ uint32_t pack_f16x2(float lo, float hi) {
    uint32_t r;
    asm("cvt.rn.f16x2.f32 %0, %1, %2;" : "=r"(r) : "f"(hi), "f"(lo));
    return r;
}
__device__ __forceinline__ uint32_t add_f16x2(uint32_t a, uint32_t b) {
    uint32_t r;
    asm("add.f16x2 %0, %1, %2;" : "=r"(r) : "r"(a), "r"(b));
    return r;
}
__device__ __forceinline__ uint32_t relu_f16x2(uint32_t a) {
    uint32_t r;
    asm("max.f16x2 %0, %1, %2;" : "=r"(r) : "r"(a), "r"(0u));
    return r;
}
// f16-accum MMA, C given explicitly (bias fold, no init MOVs)
__device__ __forceinline__ void mma_f16_init(uint32_t& d0, uint32_t& d1,
                                             uint32_t a0, uint32_t a1, uint32_t a2, uint32_t a3,
                                             uint32_t b0, uint32_t b1, uint32_t c) {
    asm volatile("mma.sync.aligned.m16n8k16.row.col.f16.f16.f16.f16 "
                 "{%0,%1}, {%2,%3,%4,%5}, {%6,%7}, {%8,%8};"
                 : "=r"(d0), "=r"(d1)
                 : "r"(a0), "r"(a1), "r"(a2), "r"(a3), "r"(b0), "r"(b1), "r"(c));
}
__device__ __forceinline__ void mma_f16_acc(uint32_t& d0, uint32_t& d1,
                                            uint32_t a0, uint32_t a1, uint32_t a2, uint32_t a3,
                                            uint32_t b0, uint32_t b1) {
    asm volatile("mma.sync.aligned.m16n8k16.row.col.f16.f16.f16.f16 "
                 "{%0,%1}, {%2,%3,%4,%5}, {%6,%7}, {%0,%1};"
                 : "+r"(d0), "+r"(d1)
                 : "r"(a0), "r"(a1), "r"(a2), "r"(a3), "r"(b0), "r"(b1));
}
// f32-accum epilogue MMA (f16 inputs)
__device__ __forceinline__ void mma_f16_f32(float& d0, float& d1, float& d2, float& d3,
                                            uint32_t a0, uint32_t a1, uint32_t a2, uint32_t a3,
                                            uint32_t b0, uint32_t b1) {
    asm volatile("mma.sync.aligned.m16n8k16.row.col.f32.f16.f16.f32 "
                 "{%0,%1,%2,%3}, {%4,%5,%6,%7}, {%8,%9}, {%0,%1,%2,%3};"
                 : "+f"(d0), "+f"(d1), "+f"(d2), "+f"(d3)
                 : "r"(a0), "r"(a1), "r"(a2), "r"(a3), "r"(b0), "r"(b1));
}

__device__ __forceinline__ uint32_t smem_u32(const void* p) {
    uint32_t a;
    asm("{ .reg .u64 t; cvta.to.shared.u64 t, %1; cvt.u32.u64 %0, t; }" : "=r"(a) : "l"(p));
    return a;
}
__device__ __forceinline__ void cp_async16(uint32_t saddr, const void* g) {
    asm volatile("cp.async.cg.shared.global [%0], [%1], 16;" :: "r"(saddr), "l"(g));
}

// ---------------------------------------------------------------------------
// prepA kernel: per (b,nbc): bf = relu(relu(binfo@W0+b0)@W1+b1); a = bf@G0w[:64]
// 256 blocks x 128 threads (2 boundary points per block).
// Also initializes d_out to G2b[0] (atomic accumulation target in main).
// ---------------------------------------------------------------------------
__global__ void __launch_bounds__(128)
prepA_kernel(const float* __restrict__ binfo,
             const float* __restrict__ W0, const float* __restrict__ b0,
             const float* __restrict__ W1, const float* __restrict__ b1,
             const float* __restrict__ G0w,
             const float* __restrict__ G2b,
             float* __restrict__ out) {
    __shared__ __align__(16) float sW1[HID * HID];
    __shared__ __align__(16) float sG0[HID * HID];
    __shared__ float sbf0[2][HID];
    __shared__ float sbf1[2][HID];

    const int tid = threadIdx.x;
    const int sub = tid >> 6;       // 0..1
    const int j   = tid & 63;
    const int bn  = blockIdx.x * 2 + sub;    // 0..511

    {   // async prefetch of big weights (overlaps with stage 0)
        uint32_t sw = smem_u32(sW1);
        uint32_t sg = smem_u32(sG0);
        #pragma unroll
        for (int i = tid; i < 1024; i += 128) cp_async16(sw + i * 16, W1 + i * 4);
        #pragma unroll
        for (int i = tid; i < 1024; i += 128) cp_async16(sg + i * 16, G0w + i * 4);
        asm volatile("cp.async.commit_group;" ::: "memory");
    }

    // init the output slice this block owns (16384 = 256 blocks * 64)
    if (tid < 64) out[blockIdx.x * 64 + tid] = G2b[0];

    // stage 0: bf0 = relu(binfo @ W0 + b0)
    const float* bi = binfo + bn * 3;
    float x0 = bi[0], x1 = bi[1], x2 = bi[2];
    sbf0[sub][j] = fmaxf(
        fmaf(x0, W0[j], fmaf(x1, W0[64 + j], fmaf(x2, W0[128 + j], b0[j]))), 0.0f);

    asm volatile("cp.async.wait_group 0;" ::: "memory");
    __syncthreads();

    // stage 1: bf1 = relu(bf0 @ W1 + b1)
    float s = b1[j];
    #pragma unroll 16
    for (int k = 0; k < HID; k++) s = fmaf(sbf0[sub][k], sW1[k * 64 + j], s);
    sbf1[sub][j] = fmaxf(s, 0.0f);
    __syncthreads();

    // stage 2: a = bf1 @ G0w[:64]
    float a = 0.0f;
    #pragma unroll 16
    for (int k = 0; k < HID; k++) a = fmaf(sbf1[sub][k], sG0[k * 64 + j], a);
    g_avec[bn * 64 + j] = a;
}

// ---------------------------------------------------------------------------
// Main kernel: fp16 m16n8k16 engine (round-13 layout) with a BALANCED static
// partition: grid = 296 CTAs (exactly 2/SM, one wave). Work = 4096 fine units
// (b | tile | chunk-of-4-nbc, chunk fastest); CTA i owns the contiguous range
// [i*512/37, (i+1)*512/37) -> 13..14 units, imbalance ~1%. Contiguity means
// <=2 (b,tile) segments per CTA, so c-rebuild / s_ap(b) reload are amortized.
// Segments flush partial sums via atomicAdd into out (pre-set to G2b).
// ---------------------------------------------------------------------------
#define WSTRIDE 68   // uint2 units per packed row; conflict-free per phase

// smem: s_ap2 128*16 uint2 (16384B) | s_w 16*68 uint2 (8704B) | 3*64 f (768B)
#define SMEM_AP_BYTES 16384
#define SMEM_W_BYTES  (16 * WSTRIDE * 8)
#define SMEM_WX_OFF   (SMEM_AP_BYTES + SMEM_W_BYTES)
#define SMEM_TOTAL    (SMEM_WX_OFF + 3 * 64 * 4)

__global__ void __launch_bounds__(256, 2)
main_kernel(const float* __restrict__ G1w,
            const float* __restrict__ G1b,
            const float* __restrict__ G2w,
            const float* __restrict__ coords,
            const float* __restrict__ G0w,
            const float* __restrict__ G0b,
            float* __restrict__ out) {
    extern __shared__ char smem[];
    uint2* s_ap2 = reinterpret_cast<uint2*>(smem);
    uint2* s_w   = reinterpret_cast<uint2*>(smem + SMEM_AP_BYTES);
    float* s_wx  = reinterpret_cast<float*>(smem + SMEM_WX_OFF);
    float* s_wy  = s_wx + 64;
    float* s_gb  = s_wy + 64;

    const int tid  = threadIdx.x;
    const int wid  = tid >> 5;
    const int lane = tid & 31;
    const int gid  = lane >> 2;    // 0..7
    const int tig  = lane & 3;     // 0..3

    // contiguous unit range for this CTA (4096 units over 296 CTAs)
    const int u0 = (int)(((long long)blockIdx.x * 512) / 37);
    const int u1 = (int)(((long long)(blockIdx.x + 1) * 512) / 37);

    // --- one-time prologue: stage weights ---
    {   // G1w -> fp16, packed per (s,tg): {W[k0],W[k0+1]} , {W[k0+8],W[k0+9]}
        #pragma unroll
        for (int idx = tid; idx < 16 * 64; idx += 256) {
            int prow = idx >> 6;            // 0..15 = s*4 + tg
            int col  = idx & 63;
            int s    = prow >> 2;
            int tg   = prow & 3;
            int k0   = 16 * s + 2 * tg;
            uint32_t w0 = pack_f16x2(G1w[k0 * 64 + col],       G1w[(k0 + 1) * 64 + col]);
            uint32_t w1 = pack_f16x2(G1w[(k0 + 8) * 64 + col], G1w[(k0 + 9) * 64 + col]);
            s_w[prow * WSTRIDE + col] = make_uint2(w0, w1);
        }
    }
    if (tid < 64) {
        s_wx[tid] = G0w[64 * 64 + tid];
        s_wy[tid] = G0w[65 * 64 + tid];
        s_gb[tid] = G0b[tid];
    }
    __syncthreads();

    // loop-invariant: bias C-operands and epilogue B fragments
    uint32_t bb[8];
    #pragma unroll
    for (int nb = 0; nb < 8; nb++) {
        float2 g = *reinterpret_cast<const float2*>(G1b + nb * 8 + 2 * tig);
        bb[nb] = pack_f16x2(g.x, g.y);
    }
    uint2 b2[4];
    #pragma unroll
    for (int kc = 0; kc < 4; kc++) {
        int k = 16 * kc + 2 * tig;
        float2 glo = *reinterpret_cast<const float2*>(G2w + k);
        float2 ghi = *reinterpret_cast<const float2*>(G2w + k + 8);
        b2[kc] = make_uint2(pack_f16x2(glo.x, glo.y), pack_f16x2(ghi.x, ghi.y));
    }
    // hoist B fragments for nb 0..1 into registers
    uint2 bwr[2][4];
    #pragma unroll
    for (int nb = 0; nb < 2; nb++)
        #pragma unroll
        for (int s = 0; s < 4; s++)
            bwr[nb][s] = s_w[(s * 4 + tig) * WSTRIDE + nb * 8 + gid];

    const float scale = 1.0f / (float)NBC;
    int cur_b = -1;

    int u = u0;
    while (u < u1) {
        const int b    = u >> 10;
        const int tile = (u >> 5) & 31;
        int segEnd = ((u >> 5) + 1) << 5;          // end of this (b,tile) group
        if (segEnd > u1) segEnd = u1;

        // (re)load s_ap for this batch (<=2 times per CTA; uniform control flow)
        if (b != cur_b) {
            __syncthreads();
            const float* abase = g_avec + (size_t)b * NBC * HID;
            #pragma unroll
            for (int idx = tid; idx < NBC * 16; idx += 256) {
                int nn = idx >> 4;
                int p  = idx & 15;
                int s  = p >> 2;
                int t  = p & 3;
                const float* row = abase + nn * 64 + 16 * s + 2 * t;
                float2 lo = *reinterpret_cast<const float2*>(row);
                float2 hi = *reinterpret_cast<const float2*>(row + 8);
                s_ap2[idx] = make_uint2(pack_f16x2(lo.x, lo.y), pack_f16x2(hi.x, hi.y));
            }
            __syncthreads();
            cur_b = b;
        }

        // rebuild c fragments for this (b, tile)
        const int rowl = tile * 128 + wid * 16 + gid;
        const int row0 = b * NINT + rowl;
        uint32_t cp0[8], cp1[8];
        {
            float cx0 = coords[(size_t)row0 * 2 + 0];
            float cy0 = coords[(size_t)row0 * 2 + 1];
            float cx1 = coords[(size_t)(row0 + 8) * 2 + 0];
            float cy1 = coords[(size_t)(row0 + 8) * 2 + 1];
            #pragma unroll
            for (int s = 0; s < 4; s++) {
                #pragma unroll
                for (int h = 0; h < 2; h++) {
                    int k = 16 * s + 2 * tig + 8 * h;
                    float wxa = s_wx[k],     wya = s_wy[k],     gba = s_gb[k];
                    float wxb = s_wx[k + 1], wyb = s_wy[k + 1], gbb = s_gb[k + 1];
                    cp0[2 * s + h] = pack_f16x2(fmaf(cx0, wxa, fmaf(cy0, wya, gba)),
                                                fmaf(cx0, wxb, fmaf(cy0, wyb, gbb)));
                    cp1[2 * s + h] = pack_f16x2(fmaf(cx1, wxa, fmaf(cy1, wya, gba)),
                                                fmaf(cx1, wxb, fmaf(cy1, wyb, gbb)));
                }
            }
        }

        // nbc range for this segment
        const int nn0 = (u & 31) * 4;
        const int nn1 = nn0 + (segEnd - u) * 4;

        float Da0 = 0.0f, Da1 = 0.0f, Da2 = 0.0f, Da3 = 0.0f;
        float Db0 = 0.0f, Db1 = 0.0f, Db2 = 0.0f, Db3 = 0.0f;

        #pragma unroll 1
        for (int nn = nn0; nn < nn1; nn++) {
            const uint2* ar = s_ap2 + nn * 16;

            // A fragments: h1 = relu(a + c), f16x2
            uint32_t A0[4], A1[4], A2v[4], A3[4];
            #pragma unroll
            for (int s = 0; s < 4; s++) {
                uint2 ap = ar[s * 4 + tig];
                A0[s]  = relu_f16x2(add_f16x2(ap.x, cp0[2 * s + 0]));
                A1[s]  = relu_f16x2(add_f16x2(ap.x, cp1[2 * s + 0]));
                A2v[s] = relu_f16x2(add_f16x2(ap.y, cp0[2 * s + 1]));
                A3[s]  = relu_f16x2(add_f16x2(ap.y, cp1[2 * s + 1]));
            }

            #pragma unroll
            for (int kc = 0; kc < 4; kc++) {
                const int nb0 = 2 * kc, nb1 = 2 * kc + 1;
                uint32_t d0, d1, f0, f1;
                {
                    uint2 w = (nb0 < 2) ? bwr[nb0][0] : s_w[tig * WSTRIDE + nb0 * 8 + gid];
                    mma_f16_init(d0, d1, A0[0], A1[0], A2v[0], A3[0], w.x, w.y, bb[nb0]);
                    #pragma unroll
                    for (int s = 1; s < 4; s++) {
                        uint2 ws = (nb0 < 2) ? bwr[nb0][s]
                                             : s_w[(s * 4 + tig) * WSTRIDE + nb0 * 8 + gid];
                        mma_f16_acc(d0, d1, A0[s], A1[s], A2v[s], A3[s], ws.x, ws.y);
                    }
                }
                {
                    uint2 w = (nb1 < 2) ? bwr[nb1][0] : s_w[tig * WSTRIDE + nb1 * 8 + gid];
                    mma_f16_init(f0, f1, A0[0], A1[0], A2v[0], A3[0], w.x, w.y, bb[nb1]);
                    #pragma unroll
                    for (int s = 1; s < 4; s++) {
                        uint2 ws = (nb1 < 2) ? bwr[nb1][s]
                                             : s_w[(s * 4 + tig) * WSTRIDE + nb1 * 8 + gid];
                        mma_f16_acc(f0, f1, A0[s], A1[s], A2v[s], A3[s], ws.x, ws.y);
                    }
                }
                // relu(h2) -> epilogue A fragments
                d0 = relu_f16x2(d0);
                d1 = relu_f16x2(d1);
                f0 = relu_f16x2(f0);
                f1 = relu_f16x2(f1);
                if (kc & 1)
                    mma_f16_f32(Db0, Db1, Db2, Db3, d0, d1, f0, f1, b2[kc].x, b2[kc].y);
                else
                    mma_f16_f32(Da0, Da1, Da2, Da3, d0, d1, f0, f1, b2[kc].x, b2[kc].y);
            }
        }

        // flush this segment's partial sums (D2 n-cols identical -> no reduce)
        if (tig == 0) {
            atomicAdd(out + row0,     (Da0 + Db0) * scale);
            atomicAdd(out + row0 + 8, (Da2 + Db2) * scale);
        }

        u = segEnd;
    }
}

// ---------------------------------------------------------------------------
// Launch.  Inputs (metadata order):
// 0 boundary_info 1 interior_coords 2 W0 3 b0 4 W1 5 b1
// 6 G0w 7 G0b 8 G1w 9 G1b 10 G2w 11 G2b 12 interior_h 13 interior_w
// ---------------------------------------------------------------------------
extern "C" void kernel_launch(void* const* d_in, const int* in_sizes, int n_in,
                              void* d_out, int out_size) {
    const float* binfo  = (const float*)d_in[0];
    const float* coords = (const float*)d_in[1];
    const float* W0     = (const float*)d_in[2];
    const float* b0     = (const float*)d_in[3];
    const float* W1     = (const float*)d_in[4];
    const float* b1     = (const float*)d_in[5];
    const float* G0w    = (const float*)d_in[6];
    const float* G0b    = (const float*)d_in[7];
    const float* G1w    = (const float*)d_in[8];
    const float* G1b    = (const float*)d_in[9];
    const float* G2w    = (const float*)d_in[10];
    const float* G2b    = (const float*)d_in[11];
    float* out          = (float*)d_out;

    cudaFuncSetAttribute(main_kernel, cudaFuncAttributeMaxDynamicSharedMemorySize, SMEM_TOTAL);

    prepA_kernel<<<256, 128>>>(binfo, W0, b0, W1, b1, G0w, G2b, out);
    main_kernel<<<296, 256, SMEM_TOTAL>>>(G1w, G1b, G2w, coords, G0w, G0b, out);
}

// round 16
// speedup vs baseline: 1.1231x; 1.0043x over previous
#include <cuda_runtime.h>
#include <cstdint>

// Problem constants (fixed by the dataset)
#define BB    4
#define NBC   128
#define NINT  4096
#define HID   64

// ---------------------------------------------------------------------------
// Device scratch (allocation-free)
// ---------------------------------------------------------------------------
__device__ float g_avec[BB * NBC * HID];              // a[b][nbc][k]

// ---------------------------------------------------------------------------
// fp16 helpers (plain sm_80+)
// ---------------------------------------------------------------------------
__device__ __forceinline__ uint32_t pack_f16x2(float lo, float hi) {
    uint32_t r;
    asm("cvt.rn.f16x2.f32 %0, %1, %2;" : "=r"(r) : "f"(hi), "f"(lo));
    return r;
}
__device__ __forceinline__ uint32_t add_f16x2(uint32_t a, uint32_t b) {
    uint32_t r;
    asm("add.f16x2 %0, %1, %2;" : "=r"(r) : "r"(a), "r"(b));
    return r;
}
__device__ __forceinline__ uint32_t relu_f16x2(uint32_t a) {
    uint32_t r;
    asm("max.f16x2 %0, %1, %2;" : "=r"(r) : "r"(a), "r"(0u));
    return r;
}
// f16-accum MMA, C given explicitly (bias fold, no init MOVs)
__device__ __forceinline__ void mma_f16_init(uint32_t& d0, uint32_t& d1,
                                             uint32_t a0, uint32_t a1, uint32_t a2, uint32_t a3,
                                             uint32_t b0, uint32_t b1, uint32_t c) {
    asm volatile("mma.sync.aligned.m16n8k16.row.col.f16.f16.f16.f16 "
                 "{%0,%1}, {%2,%3,%4,%5}, {%6,%7}, {%8,%8};"
                 : "=r"(d0), "=r"(d1)
                 : "r"(a0), "r"(a1), "r"(a2), "r"(a3), "r"(b0), "r"(b1), "r"(c));
}
__device__ __forceinline__ void mma_f16_acc(uint32_t& d0, uint32_t& d1,
                                            uint32_t a0, uint32_t a1, uint32_t a2, uint32_t a3,
                                            uint32_t b0, uint32_t b1) {
    asm volatile("mma.sync.aligned.m16n8k16.row.col.f16.f16.f16.f16 "
                 "{%0,%1}, {%2,%3,%4,%5}, {%6,%7}, {%0,%1};"
                 : "+r"(d0), "+r"(d1)
                 : "r"(a0), "r"(a1), "r"(a2), "r"(a3), "r"(b0), "r"(b1));
}
// f32-accum epilogue MMA (f16 inputs)
__device__ __forceinline__ void mma_f16_f32(float& d0, float& d1, float& d2, float& d3,
                                            uint32_t a0, uint32_t a1, uint32_t a2, uint32_t a3,
                                            uint32_t b0, uint32_t b1) {
    asm volatile("mma.sync.aligned.m16n8k16.row.col.f32.f16.f16.f32 "
                 "{%0,%1,%2,%3}, {%4,%5,%6,%7}, {%8,%9}, {%0,%1,%2,%3};"
                 : "+f"(d0), "+f"(d1), "+f"(d2), "+f"(d3)
                 : "r"(a0), "r"(a1), "r"(a2), "r"(a3), "r"(b0), "r"(b1));
}

__device__ __forceinline__ uint32_t smem_u32(const void* p) {
    uint32_t a;
    asm("{ .reg .u64 t; cvta.to.shared.u64 t, %1; cvt.u32.u64 %0, t; }" : "=r"(a) : "l"(p));
    return a;
}
__device__ __forceinline__ void cp_async16(uint32_t saddr, const void* g) {
    asm volatile("cp.async.cg.shared.global [%0], [%1], 16;" :: "r"(saddr), "l"(g));
}

// ---------------------------------------------------------------------------
// prepA kernel: per (b,nbc): bf = relu(relu(binfo@W0+b0)@W1+b1); a = bf@G0w[:64]
// 256 blocks x 128 threads (2 boundary points per block).
// Also initializes d_out to G2b[0] (atomic accumulation target in main).
// ---------------------------------------------------------------------------
__global__ void __launch_bounds__(128)
prepA_kernel(const float* __restrict__ binfo,
             const float* __restrict__ W0, const float* __restrict__ b0,
             const float* __restrict__ W1, const float* __restrict__ b1,
             const float* __restrict__ G0w,
             const float* __restrict__ G2b,
             float* __restrict__ out) {
    __shared__ __align__(16) float sW1[HID * HID];
    __shared__ __align__(16) float sG0[HID * HID];
    __shared__ float sbf0[2][HID];
    __shared__ float sbf1[2][HID];

    const int tid = threadIdx.x;
    const int sub = tid >> 6;       // 0..1
    const int j   = tid & 63;
    const int bn  = blockIdx.x * 2 + sub;    // 0..511

    {   // async prefetch of big weights (overlaps with stage 0)
        uint32_t sw = smem_u32(sW1);
        uint32_t sg = smem_u32(sG0);
        #pragma unroll
        for (int i = tid; i < 1024; i += 128) cp_async16(sw + i * 16, W1 + i * 4);
        #pragma unroll
        for (int i = tid; i < 1024; i += 128) cp_async16(sg + i * 16, G0w + i * 4);
        asm volatile("cp.async.commit_group;" ::: "memory");
    }

    // init the output slice this block owns (16384 = 256 blocks * 64)
    if (tid < 64) out[blockIdx.x * 64 + tid] = G2b[0];

    // stage 0: bf0 = relu(binfo @ W0 + b0)
    const float* bi = binfo + bn * 3;
    float x0 = bi[0], x1 = bi[1], x2 = bi[2];
    sbf0[sub][j] = fmaxf(
        fmaf(x0, W0[j], fmaf(x1, W0[64 + j], fmaf(x2, W0[128 + j], b0[j]))), 0.0f);

    asm volatile("cp.async.wait_group 0;" ::: "memory");
    __syncthreads();

    // stage 1: bf1 = relu(bf0 @ W1 + b1)
    float s = b1[j];
    #pragma unroll 16
    for (int k = 0; k < HID; k++) s = fmaf(sbf0[sub][k], sW1[k * 64 + j], s);
    sbf1[sub][j] = fmaxf(s, 0.0f);
    __syncthreads();

    // stage 2: a = bf1 @ G0w[:64]
    float a = 0.0f;
    #pragma unroll 16
    for (int k = 0; k < HID; k++) a = fmaf(sbf1[sub][k], sG0[k * 64 + j], a);
    g_avec[bn * 64 + j] = a;
}

// ---------------------------------------------------------------------------
// Main kernel: fp16 m16n8k16 engine, balanced 296-CTA partition (round 15),
// with VECTORIZED smem operand fetches:
//   s_w4:  per (nb, lane): two uint4 holding the 4 s-fragments -> 2 LDS.128
//          per nb (was 4 LDS.64); lane-linear 16B addressing, conflict-free.
//   s_ap4: per (nn, tig): two uint4 -> 2 LDS.128 per iter (was 4 LDS.64).
// Inner loop memory issues: 28 -> 14 per warp-iter, same bytes.
// ---------------------------------------------------------------------------

// smem layout (bytes):
//   s_ap4  128 nn * 4 tig * 2 half * 16B = 16384
//   s_w4   8 nb * 2 sel * 32 lane * 16B  = 8192
//   s_wx/s_wy/s_gb  3*64*4               = 768
#define SMEM_AP_BYTES 16384
#define SMEM_W_BYTES  8192
#define SMEM_WX_OFF   (SMEM_AP_BYTES + SMEM_W_BYTES)
#define SMEM_TOTAL    (SMEM_WX_OFF + 3 * 64 * 4)

__global__ void __launch_bounds__(256, 2)
main_kernel(const float* __restrict__ G1w,
            const float* __restrict__ G1b,
            const float* __restrict__ G2w,
            const float* __restrict__ coords,
            const float* __restrict__ G0w,
            const float* __restrict__ G0b,
            float* __restrict__ out) {
    extern __shared__ char smem[];
    uint4* s_ap4 = reinterpret_cast<uint4*>(smem);
    uint4* s_w4  = reinterpret_cast<uint4*>(smem + SMEM_AP_BYTES);
    float* s_wx  = reinterpret_cast<float*>(smem + SMEM_WX_OFF);
    float* s_wy  = s_wx + 64;
    float* s_gb  = s_wy + 64;

    const int tid  = threadIdx.x;
    const int wid  = tid >> 5;
    const int lane = tid & 31;
    const int gid  = lane >> 2;    // 0..7
    const int tig  = lane & 3;     // 0..3

    // contiguous unit range for this CTA (4096 units over 296 CTAs)
    const int u0 = (int)(((long long)blockIdx.x * 512) / 37);
    const int u1 = (int)(((long long)(blockIdx.x + 1) * 512) / 37);

    // --- one-time prologue: stage weights (vector-packed) ---
    {   // s_w4[nb*64 + sel*32 + ln] = {s(2sel).x, s(2sel).y, s(2sel+1).x, s(2sel+1).y}
        #pragma unroll
        for (int idx = tid; idx < 8 * 2 * 32; idx += 256) {   // 512
            int nb   = idx >> 6;
            int rest = idx & 63;
            int sel  = rest >> 5;
            int ln   = rest & 31;
            int tg   = ln & 3;
            int gd   = ln >> 2;
            int col  = nb * 8 + gd;
            int ka   = 16 * (2 * sel)     + 2 * tg;
            int kb   = 16 * (2 * sel + 1) + 2 * tg;
            uint4 v;
            v.x = pack_f16x2(G1w[ka * 64 + col],       G1w[(ka + 1) * 64 + col]);
            v.y = pack_f16x2(G1w[(ka + 8) * 64 + col], G1w[(ka + 9) * 64 + col]);
            v.z = pack_f16x2(G1w[kb * 64 + col],       G1w[(kb + 1) * 64 + col]);
            v.w = pack_f16x2(G1w[(kb + 8) * 64 + col], G1w[(kb + 9) * 64 + col]);
            s_w4[nb * 64 + sel * 32 + ln] = v;
        }
    }
    if (tid < 64) {
        s_wx[tid] = G0w[64 * 64 + tid];
        s_wy[tid] = G0w[65 * 64 + tid];
        s_gb[tid] = G0b[tid];
    }
    __syncthreads();

    // loop-invariant: bias C-operands and epilogue B fragments
    uint32_t bb[8];
    #pragma unroll
    for (int nb = 0; nb < 8; nb++) {
        float2 g = *reinterpret_cast<const float2*>(G1b + nb * 8 + 2 * tig);
        bb[nb] = pack_f16x2(g.x, g.y);
    }
    uint2 b2[4];
    #pragma unroll
    for (int kc = 0; kc < 4; kc++) {
        int k = 16 * kc + 2 * tig;
        float2 glo = *reinterpret_cast<const float2*>(G2w + k);
        float2 ghi = *reinterpret_cast<const float2*>(G2w + k + 8);
        b2[kc] = make_uint2(pack_f16x2(glo.x, glo.y), pack_f16x2(ghi.x, ghi.y));
    }
    // hoist B fragments for nb 0..1 into registers (4 uint4 = 16 regs)
    uint4 bwr4[2][2];
    #pragma unroll
    for (int nb = 0; nb < 2; nb++) {
        bwr4[nb][0] = s_w4[nb * 64 + lane];
        bwr4[nb][1] = s_w4[nb * 64 + 32 + lane];
    }

    const float scale = 1.0f / (float)NBC;
    int cur_b = -1;

    int u = u0;
    while (u < u1) {
        const int b    = u >> 10;
        const int tile = (u >> 5) & 31;
        int segEnd = ((u >> 5) + 1) << 5;          // end of this (b,tile) group
        if (segEnd > u1) segEnd = u1;

        // (re)load s_ap4 for this batch (<=2 times per CTA; uniform control flow)
        if (b != cur_b) {
            __syncthreads();
            const float* abase = g_avec + (size_t)b * NBC * HID;
            #pragma unroll
            for (int idx = tid; idx < NBC * 8; idx += 256) {   // 1024
                int nn   = idx >> 3;
                int rest = idx & 7;
                int tg   = rest >> 1;
                int half = rest & 1;
                const float* r0 = abase + nn * 64 + 16 * (2 * half)     + 2 * tg;
                const float* r1 = abase + nn * 64 + 16 * (2 * half + 1) + 2 * tg;
                float2 l0 = *reinterpret_cast<const float2*>(r0);
                float2 h0 = *reinterpret_cast<const float2*>(r0 + 8);
                float2 l1 = *reinterpret_cast<const float2*>(r1);
                float2 h1 = *reinterpret_cast<const float2*>(r1 + 8);
                uint4 v;
                v.x = pack_f16x2(l0.x, l0.y);
                v.y = pack_f16x2(h0.x, h0.y);
                v.z = pack_f16x2(l1.x, l1.y);
                v.w = pack_f16x2(h1.x, h1.y);
                s_ap4[idx] = v;
            }
            __syncthreads();
            cur_b = b;
        }

        // rebuild c fragments for this (b, tile)
        const int rowl = tile * 128 + wid * 16 + gid;
        const int row0 = b * NINT + rowl;
        uint32_t cp0[8], cp1[8];
        {
            float cx0 = coords[(size_t)row0 * 2 + 0];
            float cy0 = coords[(size_t)row0 * 2 + 1];
            float cx1 = coords[(size_t)(row0 + 8) * 2 + 0];
            float cy1 = coords[(size_t)(row0 + 8) * 2 + 1];
            #pragma unroll
            for (int s = 0; s < 4; s++) {
                #pragma unroll
                for (int h = 0; h < 2; h++) {
                    int k = 16 * s + 2 * tig + 8 * h;
                    float wxa = s_wx[k],     wya = s_wy[k],     gba = s_gb[k];
                    float wxb = s_wx[k + 1], wyb = s_wy[k + 1], gbb = s_gb[k + 1];
                    cp0[2 * s + h] = pack_f16x2(fmaf(cx0, wxa, fmaf(cy0, wya, gba)),
                                                fmaf(cx0, wxb, fmaf(cy0, wyb, gbb)));
                    cp1[2 * s + h] = pack_f16x2(fmaf(cx1, wxa, fmaf(cy1, wya, gba)),
                                                fmaf(cx1, wxb, fmaf(cy1, wyb, gbb)));
                }
            }
        }

        // nbc range for this segment
        const int nn0 = (u & 31) * 4;
        const int nn1 = nn0 + (segEnd - u) * 4;

        float Da0 = 0.0f, Da1 = 0.0f, Da2 = 0.0f, Da3 = 0.0f;
        float Db0 = 0.0f, Db1 = 0.0f, Db2 = 0.0f, Db3 = 0.0f;

        #pragma unroll 1
        for (int nn = nn0; nn < nn1; nn++) {
            // A operands: 2 x LDS.128 (4-address broadcast)
            uint4 apA = s_ap4[nn * 8 + tig * 2 + 0];   // {s0.x, s0.h, s1.x, s1.h}
            uint4 apB = s_ap4[nn * 8 + tig * 2 + 1];   // {s2.x, s2.h, s3.x, s3.h}

            // A fragments: h1 = relu(a + c), f16x2
            uint32_t A0[4], A1[4], A2v[4], A3[4];
            A0[0]  = relu_f16x2(add_f16x2(apA.x, cp0[0]));
            A1[0]  = relu_f16x2(add_f16x2(apA.x, cp1[0]));
            A2v[0] = relu_f16x2(add_f16x2(apA.y, cp0[1]));
            A3[0]  = relu_f16x2(add_f16x2(apA.y, cp1[1]));
            A0[1]  = relu_f16x2(add_f16x2(apA.z, cp0[2]));
            A1[1]  = relu_f16x2(add_f16x2(apA.z, cp1[2]));
            A2v[1] = relu_f16x2(add_f16x2(apA.w, cp0[3]));
            A3[1]  = relu_f16x2(add_f16x2(apA.w, cp1[3]));
            A0[2]  = relu_f16x2(add_f16x2(apB.x, cp0[4]));
            A1[2]  = relu_f16x2(add_f16x2(apB.x, cp1[4]));
            A2v[2] = relu_f16x2(add_f16x2(apB.y, cp0[5]));
            A3[2]  = relu_f16x2(add_f16x2(apB.y, cp1[5]));
            A0[3]  = relu_f16x2(add_f16x2(apB.z, cp0[6]));
            A1[3]  = relu_f16x2(add_f16x2(apB.z, cp1[6]));
            A2v[3] = relu_f16x2(add_f16x2(apB.w, cp0[7]));
            A3[3]  = relu_f16x2(add_f16x2(apB.w, cp1[7]));

            #pragma unroll
            for (int kc = 0; kc < 4; kc++) {
                const int nb0 = 2 * kc, nb1 = 2 * kc + 1;
                uint32_t d0, d1, f0, f1;
                {
                    uint4 q0 = (nb0 < 2) ? bwr4[nb0][0] : s_w4[nb0 * 64 + lane];
                    uint4 q1 = (nb0 < 2) ? bwr4[nb0][1] : s_w4[nb0 * 64 + 32 + lane];
                    mma_f16_init(d0, d1, A0[0], A1[0], A2v[0], A3[0], q0.x, q0.y, bb[nb0]);
                    mma_f16_acc (d0, d1, A0[1], A1[1], A2v[1], A3[1], q0.z, q0.w);
                    mma_f16_acc (d0, d1, A0[2], A1[2], A2v[2], A3[2], q1.x, q1.y);
                    mma_f16_acc (d0, d1, A0[3], A1[3], A2v[3], A3[3], q1.z, q1.w);
                }
                {
                    uint4 q0 = (nb1 < 2) ? bwr4[nb1][0] : s_w4[nb1 * 64 + lane];
                    uint4 q1 = (nb1 < 2) ? bwr4[nb1][1] : s_w4[nb1 * 64 + 32 + lane];
                    mma_f16_init(f0, f1, A0[0], A1[0], A2v[0], A3[0], q0.x, q0.y, bb[nb1]);
                    mma_f16_acc (f0, f1, A0[1], A1[1], A2v[1], A3[1], q0.z, q0.w);
                    mma_f16_acc (f0, f1, A0[2], A1[2], A2v[2], A3[2], q1.x, q1.y);
                    mma_f16_acc (f0, f1, A0[3], A1[3], A2v[3], A3[3], q1.z, q1.w);
                }
                // relu(h2) -> epilogue A fragments
                d0 = relu_f16x2(d0);
                d1 = relu_f16x2(d1);
                f0 = relu_f16x2(f0);
                f1 = relu_f16x2(f1);
                if (kc & 1)
                    mma_f16_f32(Db0, Db1, Db2, Db3, d0, d1, f0, f1, b2[kc].x, b2[kc].y);
                else
                    mma_f16_f32(Da0, Da1, Da2, Da3, d0, d1, f0, f1, b2[kc].x, b2[kc].y);
            }
        }

        // flush this segment's partial sums (D2 n-cols identical -> no reduce)
        if (tig == 0) {
            atomicAdd(out + row0,     (Da0 + Db0) * scale);
            atomicAdd(out + row0 + 8, (Da2 + Db2) * scale);
        }

        u = segEnd;
    }
}

// ---------------------------------------------------------------------------
// Launch.  Inputs (metadata order):
// 0 boundary_info 1 interior_coords 2 W0 3 b0 4 W1 5 b1
// 6 G0w 7 G0b 8 G1w 9 G1b 10 G2w 11 G2b 12 interior_h 13 interior_w
// ---------------------------------------------------------------------------
extern "C" void kernel_launch(void* const* d_in, const int* in_sizes, int n_in,
                              void* d_out, int out_size) {
    const float* binfo  = (const float*)d_in[0];
    const float* coords = (const float*)d_in[1];
    const float* W0     = (const float*)d_in[2];
    const float* b0     = (const float*)d_in[3];
    const float* W1     = (const float*)d_in[4];
    const float* b1     = (const float*)d_in[5];
    const float* G0w    = (const float*)d_in[6];
    const float* G0b    = (const float*)d_in[7];
    const float* G1w    = (const float*)d_in[8];
    const float* G1b    = (const float*)d_in[9];
    const float* G2w    = (const float*)d_in[10];
    const float* G2b    = (const float*)d_in[11];
    float* out          = (float*)d_out;

    cudaFuncSetAttribute(main_kernel, cudaFuncAttributeMaxDynamicSharedMemorySize, SMEM_TOTAL);

    prepA_kernel<<<256, 128>>>(binfo, W0, b0, W1, b1, G0w, G2b, out);
    main_kernel<<<296, 256, SMEM_TOTAL>>>(G1w, G1b, G2w, coords, G0w, G0b, out);
}